// round 9
// baseline (speedup 1.0000x reference)
#include <cuda_runtime.h>
#include <cuda_fp16.h>
#include <cstdint>

#define BB 4
#define NN 4096
#define FF 128
#define NIT 256           // 4096 / 16 j-tiles

// ---------------- scratch (no allocations allowed) ----------------
__device__ uint4  g_Wh[(size_t)BB * FF * NN / 8];    // WhT fp16 [b][f][j], 4MB
__device__ float  g_si[BB * NN];
__device__ float2 g_uv[BB * NN];                     // {e^{sj}, e^{0.2 sj}}

// ---------------- helpers ----------------
__device__ __forceinline__ unsigned long long pack2(float lo, float hi) {
    unsigned long long r; asm("mov.b64 %0, {%1, %2};" : "=l"(r) : "f"(lo), "f"(hi)); return r;
}
__device__ __forceinline__ unsigned long long bcast2(float v) {
    unsigned long long r; asm("mov.b64 %0, {%1, %1};" : "=l"(r) : "f"(v)); return r;
}
__device__ __forceinline__ void fma2(unsigned long long& d, unsigned long long a, unsigned long long b) {
    asm("fma.rn.f32x2 %0, %1, %2, %0;" : "+l"(d) : "l"(a), "l"(b));
}
__device__ __forceinline__ float2 unpack2(unsigned long long v) {
    float2 f; asm("mov.b64 {%0, %1}, %2;" : "=f"(f.x), "=f"(f.y) : "l"(v)); return f;
}
// pack two floats -> fp16x2 (first arg low half), as uint32
__device__ __forceinline__ uint32_t pkhf2(float lo, float hi) {
    uint32_t r;
    asm("{ .reg .f16 l, h; cvt.rn.f16.f32 l, %1; cvt.rn.f16.f32 h, %2; mov.b32 %0, {l, h}; }"
        : "=r"(r) : "f"(lo), "f"(hi));
    return r;
}
// unpack fp16x2 -> two floats
__device__ __forceinline__ float2 uphf2(uint32_t v) {
    float2 f;
    asm("{ .reg .f16 l, h; mov.b32 {l, h}, %2; cvt.f32.f16 %0, l; cvt.f32.f16 %1, h; }"
        : "=f"(f.x), "=f"(f.y) : "r"(v));
    return f;
}
__device__ __forceinline__ void mma_fp16(float* c, uint32_t a0, uint32_t a1,
                                         uint32_t a2, uint32_t a3,
                                         uint32_t b0, uint32_t b1) {
    asm volatile(
        "mma.sync.aligned.m16n8k16.row.col.f32.f16.f16.f32 "
        "{%0,%1,%2,%3}, {%4,%5,%6,%7}, {%8,%9}, {%0,%1,%2,%3};"
        : "+f"(c[0]), "+f"(c[1]), "+f"(c[2]), "+f"(c[3])
        : "r"(a0), "r"(a1), "r"(a2), "r"(a3), "r"(b0), "r"(b1));
}

// =====================================================================
// Kernel A: Wh = h @ W ; 32 rows x 128 f per CTA, 256 threads.
// Epilogue: fp16 store WhT[b][f][j] + si/sj/uv computed from fp32 acc.
// =====================================================================
__global__ void __launch_bounds__(256) k_wh(const float* __restrict__ h,
                                            const float* __restrict__ W,
                                            const float* __restrict__ a) {
    const int b = blockIdx.y;
    const int i0 = blockIdx.x * 32;

    __shared__ float hsT[32][40];    // [k][r], padded
    __shared__ float Ws[32][128];    // [k][f]
    __shared__ float aS[256];

    const int tid = threadIdx.x;
    aS[tid] = a[tid];
    const int fgrp = tid & 31, rgrp = tid >> 5;
    const int rbase = rgrp * 4, fbase = fgrp * 4;

    unsigned long long acc[4][2];
#pragma unroll
    for (int r = 0; r < 4; r++) { acc[r][0] = 0ULL; acc[r][1] = 0ULL; }

    for (int k0 = 0; k0 < FF; k0 += 32) {
        __syncthreads();
        {   // h tile: 32 rows x 32 k (one float4 per thread), transposed store
            int r = tid >> 3, kq = tid & 7;
            float4 v = *(const float4*)(h + ((size_t)(b * NN + i0 + r)) * FF + k0 + kq * 4);
            hsT[kq * 4 + 0][r] = v.x;
            hsT[kq * 4 + 1][r] = v.y;
            hsT[kq * 4 + 2][r] = v.z;
            hsT[kq * 4 + 3][r] = v.w;
        }
#pragma unroll
        for (int q = 0; q < 4; q++) {   // W chunk: 32 k x 128 f
            int idx = tid + 256 * q;
            int kk = idx >> 5, fq = idx & 31;
            *(float4*)&Ws[kk][fq * 4] = *(const float4*)(W + (size_t)(k0 + kk) * FF + fq * 4);
        }
        __syncthreads();

#pragma unroll 8
        for (int kk = 0; kk < 32; kk++) {
            float4 hr = *(float4*)&hsT[kk][rbase];
            float4 wf = *(float4*)&Ws[kk][fbase];
            unsigned long long w01 = pack2(wf.x, wf.y);
            unsigned long long w23 = pack2(wf.z, wf.w);
            float hv[4] = {hr.x, hr.y, hr.z, hr.w};
#pragma unroll
            for (int r = 0; r < 4; r++) {
                unsigned long long hb = bcast2(hv[r]);
                fma2(acc[r][0], hb, w01);
                fma2(acc[r][1], hb, w23);
            }
        }
    }

    float va[4][4];
#pragma unroll
    for (int r = 0; r < 4; r++) {
        float2 t0 = unpack2(acc[r][0]);
        float2 t1 = unpack2(acc[r][1]);
        va[r][0] = t0.x; va[r][1] = t0.y; va[r][2] = t1.x; va[r][3] = t1.y;
    }

    // fp16 store transposed: [b][f][j]
#pragma unroll
    for (int f = 0; f < 4; f++) {
        uint32_t h01 = pkhf2(va[0][f], va[1][f]);
        uint32_t h23 = pkhf2(va[2][f], va[3][f]);
        size_t idx = ((size_t)(b * FF) + fbase + f) * NN + i0 + rbase;  // fp16 elements
        *(uint2*)((__half*)g_Wh + idx) = make_uint2(h01, h23);
    }

    // si/sj from fp32 accumulators: warp reduce over fgrp (f dimension)
    float psi[4], psj[4];
#pragma unroll
    for (int r = 0; r < 4; r++) {
        float si = 0.f, sj = 0.f;
#pragma unroll
        for (int f = 0; f < 4; f++) {
            si += va[r][f] * aS[fbase + f];
            sj += va[r][f] * aS[FF + fbase + f];
        }
#pragma unroll
        for (int o = 16; o; o >>= 1) {
            si += __shfl_xor_sync(0xFFFFFFFFu, si, o);
            sj += __shfl_xor_sync(0xFFFFFFFFu, sj, o);
        }
        psi[r] = si; psj[r] = sj;
    }
    if (fgrp == 0) {
#pragma unroll
        for (int r = 0; r < 4; r++) {
            int row = b * NN + i0 + rbase + r;
            g_si[row] = psi[r];
            g_uv[row] = make_float2(__expf(psj[r]), __expf(0.2f * psj[r]));
        }
    }
}

// =====================================================================
// Kernel C: fused masked-softmax + P @ Wh via mma.sync fp16 (2-term) + ELU
// 512 threads / 16 warps: warp = 16 rows x 64 f (f split across warp pairs)
// -> 4 warps per SMSP for latency hiding.
// =====================================================================
__global__ void __launch_bounds__(512, 1) k_attn(const int* __restrict__ adj,
                                                 float* __restrict__ out) {
    __shared__ float2 uvS[NN];          // 32 KB
    __shared__ uint4  stg4[512];        // 8 KB: 2 stages x 128 f x 32B
    char* stg = (char*)stg4;

    const int tid = threadIdx.x;
    const int lane = tid & 31, w = tid >> 5;
    const int c = lane & 3, fq = lane >> 2;
    const int rg = w & 7;              // row group (0..7)
    const int fh = w >> 3;             // f half (0..1)
    const int b = blockIdx.y;
    const int i0 = blockIdx.x * 128;

#pragma unroll
    for (int k = 0; k < 8; k++) {
        int idx = tid + 512 * k;
        uvS[idx] = g_uv[b * NN + idx];
    }

    const int r0 = i0 + rg * 16 + fq;
    const int r1 = r0 + 8;
    const float si0 = g_si[b * NN + r0];
    const float si1 = g_si[b * NN + r1];
    const float c10 = __expf(si0), c20 = __expf(0.2f * si0), th0 = __expf(-si0);
    const float c11 = __expf(si1), c21 = __expf(0.2f * si1), th1 = __expf(-si1);

    const int2* a00 = (const int2*)(adj + ((size_t)(b * NN + r0)) * NN + 2 * c);
    const int2* a10 = (const int2*)(adj + ((size_t)(b * NN + r1)) * NN + 2 * c);

    // staging role (threads 0..255 only): thread -> (f row, 16B half), chunk-swizzled
    const int f = tid >> 1;
    const int hh = tid & 1;
    const bool stager = (tid < 256);
    const uint4* src = g_Wh + (size_t)(b * FF + (f & 127)) * (NN / 8);
    char* dst0 = stg + (f & 127) * 32 + 16 * (hh ^ ((f >> 2) & 1));

    // consumer B addressing (nt-independent chunk swizzle)
    const int sfl = (fq >> 2) & 1;
    const int off0 = 16 * sfl + 4 * c;
    const int off1 = 16 * (sfl ^ 1) + 4 * c;
    const char* bb = stg + fh * 2048 + fq * 32;    // this warp's 8-nt f-half
    const float2* uvp = uvS + 2 * c;

    float acc[8][4];
#pragma unroll
    for (int nt = 0; nt < 8; nt++)
#pragma unroll
        for (int k = 0; k < 4; k++) acc[nt][k] = 0.f;
    float z0 = 0.f, z1 = 0.f;

    // prologue prefetch
    uint4 cb = make_uint4(0, 0, 0, 0);
    if (stager) cb = src[hh];
    int2 A00 = __ldcs(a00), A01 = __ldcs(a00 + 4);
    int2 A10 = __ldcs(a10), A11 = __ldcs(a10 + 4);

    auto compute = [&](int tc) {
        const int J = tc * 16;
        float4 uvA = *(const float4*)(uvp + J);
        float4 uvB = *(const float4*)(uvp + J + 8);
        float p00 = A00.x > 0 ? (uvA.x > th0 ? c10 * uvA.x : c20 * uvA.y) : 0.f;
        float p01 = A00.y > 0 ? (uvA.z > th0 ? c10 * uvA.z : c20 * uvA.w) : 0.f;
        float p08 = A01.x > 0 ? (uvB.x > th0 ? c10 * uvB.x : c20 * uvB.y) : 0.f;
        float p09 = A01.y > 0 ? (uvB.z > th0 ? c10 * uvB.z : c20 * uvB.w) : 0.f;
        float p10 = A10.x > 0 ? (uvA.x > th1 ? c11 * uvA.x : c21 * uvA.y) : 0.f;
        float p11 = A10.y > 0 ? (uvA.z > th1 ? c11 * uvA.z : c21 * uvA.w) : 0.f;
        float p18 = A11.x > 0 ? (uvB.x > th1 ? c11 * uvB.x : c21 * uvB.y) : 0.f;
        float p19 = A11.y > 0 ? (uvB.z > th1 ? c11 * uvB.z : c21 * uvB.w) : 0.f;
        z0 += (p00 + p01) + (p08 + p09);
        z1 += (p10 + p11) + (p18 + p19);

        if (tc + 1 < NIT) {
            int o = (tc + 1) * 8;
            A00 = __ldcs(a00 + o); A01 = __ldcs(a00 + o + 4);
            A10 = __ldcs(a10 + o); A11 = __ldcs(a10 + o + 4);
        }

        // fp16 hi/lo split -> A fragments
        uint32_t ah0 = pkhf2(p00, p01), ah1 = pkhf2(p10, p11);
        uint32_t ah2 = pkhf2(p08, p09), ah3 = pkhf2(p18, p19);
        float2 f0 = uphf2(ah0), f1 = uphf2(ah1), f2 = uphf2(ah2), f3 = uphf2(ah3);
        uint32_t al0 = pkhf2(p00 - f0.x, p01 - f0.y);
        uint32_t al1 = pkhf2(p10 - f1.x, p11 - f1.y);
        uint32_t al2 = pkhf2(p08 - f2.x, p09 - f2.y);
        uint32_t al3 = pkhf2(p18 - f3.x, p19 - f3.y);

        const char* sbb = bb + (tc & 1) * 4096;
        uint32_t bv[16];
#pragma unroll
        for (int nt = 0; nt < 8; nt++) {
            bv[2 * nt]     = *(const uint32_t*)(sbb + nt * 256 + off0);
            bv[2 * nt + 1] = *(const uint32_t*)(sbb + nt * 256 + off1);
        }
#pragma unroll
        for (int nt = 0; nt < 8; nt++)
            mma_fp16(acc[nt], ah0, ah1, ah2, ah3, bv[2 * nt], bv[2 * nt + 1]);
#pragma unroll
        for (int nt = 0; nt < 8; nt++)
            mma_fp16(acc[nt], al0, al1, al2, al3, bv[2 * nt], bv[2 * nt + 1]);
    };

#pragma unroll 1
    for (int t = 0; t < NIT; t++) {
        __syncthreads();
        // stage tile t (chunk 2t+hh of row f) into buf t&1
        if (stager) {
            *(uint4*)(dst0 + (t & 1) * 4096) = cb;
            if (t + 1 < NIT) cb = src[2 * (t + 1) + hh];
        }
        if (t > 0) compute(t - 1);
    }
    __syncthreads();
    compute(NIT - 1);

    // Z reduction over the 4 lanes sharing a row
    z0 += __shfl_xor_sync(0xFFFFFFFFu, z0, 1);
    z0 += __shfl_xor_sync(0xFFFFFFFFu, z0, 2);
    z1 += __shfl_xor_sync(0xFFFFFFFFu, z1, 1);
    z1 += __shfl_xor_sync(0xFFFFFFFFu, z1, 2);
    const float iz0 = 1.0f / z0;
    const float iz1 = 1.0f / z1;

    float* o0 = out + ((size_t)(b * NN + r0)) * FF + fh * 64 + 2 * c;
    float* o1 = out + ((size_t)(b * NN + r1)) * FF + fh * 64 + 2 * c;
#pragma unroll
    for (int nt = 0; nt < 8; nt++) {
        float x0 = acc[nt][0] * iz0, x1 = acc[nt][1] * iz0;
        float y0 = acc[nt][2] * iz1, y1 = acc[nt][3] * iz1;
        x0 = x0 > 0.f ? x0 : (__expf(x0) - 1.0f);
        x1 = x1 > 0.f ? x1 : (__expf(x1) - 1.0f);
        y0 = y0 > 0.f ? y0 : (__expf(y0) - 1.0f);
        y1 = y1 > 0.f ? y1 : (__expf(y1) - 1.0f);
        *(float2*)(o0 + nt * 8) = make_float2(x0, x1);
        *(float2*)(o1 + nt * 8) = make_float2(y0, y1);
    }
}

// =====================================================================
extern "C" void kernel_launch(void* const* d_in, const int* in_sizes, int n_in,
                              void* d_out, int out_size) {
    const float* h   = (const float*)d_in[0];
    const int*   adj = (const int*)d_in[1];
    const float* W   = (const float*)d_in[2];
    const float* a   = (const float*)d_in[3];
    float* out = (float*)d_out;

    k_wh<<<dim3(NN / 32, BB), 256>>>(h, W, a);
    k_attn<<<dim3(NN / 128, BB), 512>>>(adj, out);
}

// round 10
// speedup vs baseline: 1.2073x; 1.2073x over previous
#include <cuda_runtime.h>
#include <cuda_fp16.h>
#include <cstdint>

#define BB 4
#define NN 4096
#define FF 128
#define NIT 256           // 4096 / 16 j-tiles

// ---------------- scratch (no allocations allowed) ----------------
__device__ uint4  g_Wh[(size_t)BB * FF * NN / 8];    // WhT fp16 [b][f][j], 4MB
__device__ float  g_si[BB * NN];
__device__ float2 g_uv[BB * NN];                     // {e^{sj}, e^{0.2 sj}}

// ---------------- helpers ----------------
__device__ __forceinline__ uint32_t smem_u32(const void* p) {
    uint32_t a;
    asm("{ .reg .u64 t; cvta.to.shared.u64 t, %1; cvt.u32.u64 %0, t; }" : "=r"(a) : "l"(p));
    return a;
}
__device__ __forceinline__ unsigned long long pack2(float lo, float hi) {
    unsigned long long r; asm("mov.b64 %0, {%1, %2};" : "=l"(r) : "f"(lo), "f"(hi)); return r;
}
__device__ __forceinline__ unsigned long long bcast2(float v) {
    unsigned long long r; asm("mov.b64 %0, {%1, %1};" : "=l"(r) : "f"(v)); return r;
}
__device__ __forceinline__ void fma2(unsigned long long& d, unsigned long long a, unsigned long long b) {
    asm("fma.rn.f32x2 %0, %1, %2, %0;" : "+l"(d) : "l"(a), "l"(b));
}
__device__ __forceinline__ float2 unpack2(unsigned long long v) {
    float2 f; asm("mov.b64 {%0, %1}, %2;" : "=f"(f.x), "=f"(f.y) : "l"(v)); return f;
}
// pack two floats -> fp16x2 (first arg low half), as uint32
__device__ __forceinline__ uint32_t pkhf2(float lo, float hi) {
    uint32_t r;
    asm("{ .reg .f16 l, h; cvt.rn.f16.f32 l, %1; cvt.rn.f16.f32 h, %2; mov.b32 %0, {l, h}; }"
        : "=r"(r) : "f"(lo), "f"(hi));
    return r;
}
// unpack fp16x2 -> two floats
__device__ __forceinline__ float2 uphf2(uint32_t v) {
    float2 f;
    asm("{ .reg .f16 l, h; mov.b32 {l, h}, %2; cvt.f32.f16 %0, l; cvt.f32.f16 %1, h; }"
        : "=f"(f.x), "=f"(f.y) : "r"(v));
    return f;
}
__device__ __forceinline__ void mma_fp16(float* c, uint32_t a0, uint32_t a1,
                                         uint32_t a2, uint32_t a3,
                                         uint32_t b0, uint32_t b1) {
    asm volatile(
        "mma.sync.aligned.m16n8k16.row.col.f32.f16.f16.f32 "
        "{%0,%1,%2,%3}, {%4,%5,%6,%7}, {%8,%9}, {%0,%1,%2,%3};"
        : "+f"(c[0]), "+f"(c[1]), "+f"(c[2]), "+f"(c[3])
        : "r"(a0), "r"(a1), "r"(a2), "r"(a3), "r"(b0), "r"(b1));
}
__device__ __forceinline__ void ldsm_x4(uint32_t addr, uint32_t& r0, uint32_t& r1,
                                        uint32_t& r2, uint32_t& r3) {
    asm volatile("ldmatrix.sync.aligned.m8n8.x4.shared.b16 {%0,%1,%2,%3}, [%4];"
                 : "=r"(r0), "=r"(r1), "=r"(r2), "=r"(r3) : "r"(addr));
}

// =====================================================================
// Kernel A: Wh = h @ W ; 32 rows x 128 f per CTA, 256 threads.
// Epilogue: fp16 store WhT[b][f][j] + si/sj/uv computed from fp32 acc.
// =====================================================================
__global__ void __launch_bounds__(256) k_wh(const float* __restrict__ h,
                                            const float* __restrict__ W,
                                            const float* __restrict__ a) {
    const int b = blockIdx.y;
    const int i0 = blockIdx.x * 32;

    __shared__ float hsT[32][40];    // [k][r], padded
    __shared__ float Ws[32][128];    // [k][f]
    __shared__ float aS[256];

    const int tid = threadIdx.x;
    aS[tid] = a[tid];
    const int fgrp = tid & 31, rgrp = tid >> 5;
    const int rbase = rgrp * 4, fbase = fgrp * 4;

    unsigned long long acc[4][2];
#pragma unroll
    for (int r = 0; r < 4; r++) { acc[r][0] = 0ULL; acc[r][1] = 0ULL; }

    for (int k0 = 0; k0 < FF; k0 += 32) {
        __syncthreads();
        {   // h tile: 32 rows x 32 k (one float4 per thread), transposed store
            int r = tid >> 3, kq = tid & 7;
            float4 v = *(const float4*)(h + ((size_t)(b * NN + i0 + r)) * FF + k0 + kq * 4);
            hsT[kq * 4 + 0][r] = v.x;
            hsT[kq * 4 + 1][r] = v.y;
            hsT[kq * 4 + 2][r] = v.z;
            hsT[kq * 4 + 3][r] = v.w;
        }
#pragma unroll
        for (int q = 0; q < 4; q++) {   // W chunk: 32 k x 128 f
            int idx = tid + 256 * q;
            int kk = idx >> 5, fq = idx & 31;
            *(float4*)&Ws[kk][fq * 4] = *(const float4*)(W + (size_t)(k0 + kk) * FF + fq * 4);
        }
        __syncthreads();

#pragma unroll 8
        for (int kk = 0; kk < 32; kk++) {
            float4 hr = *(float4*)&hsT[kk][rbase];
            float4 wf = *(float4*)&Ws[kk][fbase];
            unsigned long long w01 = pack2(wf.x, wf.y);
            unsigned long long w23 = pack2(wf.z, wf.w);
            float hv[4] = {hr.x, hr.y, hr.z, hr.w};
#pragma unroll
            for (int r = 0; r < 4; r++) {
                unsigned long long hb = bcast2(hv[r]);
                fma2(acc[r][0], hb, w01);
                fma2(acc[r][1], hb, w23);
            }
        }
    }

    float va[4][4];
#pragma unroll
    for (int r = 0; r < 4; r++) {
        float2 t0 = unpack2(acc[r][0]);
        float2 t1 = unpack2(acc[r][1]);
        va[r][0] = t0.x; va[r][1] = t0.y; va[r][2] = t1.x; va[r][3] = t1.y;
    }

    // fp16 store transposed: [b][f][j]
#pragma unroll
    for (int f = 0; f < 4; f++) {
        uint32_t h01 = pkhf2(va[0][f], va[1][f]);
        uint32_t h23 = pkhf2(va[2][f], va[3][f]);
        size_t idx = ((size_t)(b * FF) + fbase + f) * NN + i0 + rbase;  // fp16 elements
        *(uint2*)((__half*)g_Wh + idx) = make_uint2(h01, h23);
    }

    // si/sj from fp32 accumulators: warp reduce over fgrp (f dimension)
    float psi[4], psj[4];
#pragma unroll
    for (int r = 0; r < 4; r++) {
        float si = 0.f, sj = 0.f;
#pragma unroll
        for (int f = 0; f < 4; f++) {
            si += va[r][f] * aS[fbase + f];
            sj += va[r][f] * aS[FF + fbase + f];
        }
#pragma unroll
        for (int o = 16; o; o >>= 1) {
            si += __shfl_xor_sync(0xFFFFFFFFu, si, o);
            sj += __shfl_xor_sync(0xFFFFFFFFu, sj, o);
        }
        psi[r] = si; psj[r] = sj;
    }
    if (fgrp == 0) {
#pragma unroll
        for (int r = 0; r < 4; r++) {
            int row = b * NN + i0 + rbase + r;
            g_si[row] = psi[r];
            g_uv[row] = make_float2(__expf(psj[r]), __expf(0.2f * psj[r]));
        }
    }
}

// =====================================================================
// Kernel C: fused masked-softmax + P @ Wh via mma.sync fp16 (1-term) + ELU
// B fragments via ldmatrix.x4; adj prefetched 2 tiles deep.
// CTA = 128 i-rows x 128 f, 8 warps, j tiles of 16, double-buffered B.
// =====================================================================
__global__ void __launch_bounds__(256, 1) k_attn(const int* __restrict__ adj,
                                                 float* __restrict__ out) {
    __shared__ float2 uvS[NN];          // 32 KB
    __shared__ uint4  stg4[512];        // 8 KB: 2 stages x 128 f x 32B
    char* stg = (char*)stg4;

    const int tid = threadIdx.x;
    const int lane = tid & 31, w = tid >> 5;
    const int c = lane & 3, fq = lane >> 2;
    const int b = blockIdx.y;
    const int i0 = blockIdx.x * 128;

#pragma unroll
    for (int k = 0; k < 16; k++) {
        int idx = tid + 256 * k;
        uvS[idx] = g_uv[b * NN + idx];
    }

    const int r0 = i0 + w * 16 + fq;
    const int r1 = r0 + 8;
    const float si0 = g_si[b * NN + r0];
    const float si1 = g_si[b * NN + r1];
    const float c10 = __expf(si0), c20 = __expf(0.2f * si0), th0 = __expf(-si0);
    const float c11 = __expf(si1), c21 = __expf(0.2f * si1), th1 = __expf(-si1);

    const int2* a00 = (const int2*)(adj + ((size_t)(b * NN + r0)) * NN + 2 * c);
    const int2* a10 = (const int2*)(adj + ((size_t)(b * NN + r1)) * NN + 2 * c);

    // staging role: thread -> (f row, 16B half), chunk-swizzled
    const int f = tid >> 1;
    const int hh = tid & 1;
    const uint4* src = g_Wh + (size_t)(b * FF + f) * (NN / 8);   // 512 uint4 per row
    char* dst0 = stg + f * 32 + 16 * (hh ^ ((f >> 2) & 1));

    // ldmatrix per-lane base: lane&7 = matrix row (f offset), lane>>3 = matrix id
    // matrix id m: half = m&1 (j half), nto = m>>1 (nt offset within pair)
    const int l8 = lane & 7;
    const int mm = lane >> 3;
    const uint32_t stgU = smem_u32(stg);
    const uint32_t lmBase = stgU +
        (uint32_t)(l8 * 32 + 16 * ((mm & 1) ^ ((l8 >> 2) & 1)) + (mm >> 1) * 256);

    const float2* uvp = uvS + 2 * c;

    float acc[16][4];
#pragma unroll
    for (int nt = 0; nt < 16; nt++)
#pragma unroll
        for (int k = 0; k < 4; k++) acc[nt][k] = 0.f;
    float z0 = 0.f, z1 = 0.f;

    // prologue prefetch: adj for tiles 0 and 1, Wh chunk for tile 0
    int2 Pa0 = __ldcs(a00),     Pa1 = __ldcs(a00 + 4);
    int2 Pa2 = __ldcs(a10),     Pa3 = __ldcs(a10 + 4);
    int2 Pb0 = __ldcs(a00 + 8), Pb1 = __ldcs(a00 + 12);
    int2 Pb2 = __ldcs(a10 + 8), Pb3 = __ldcs(a10 + 12);
    uint4 cb = src[hh];

    auto compute = [&](int tc, int2& B00, int2& B01, int2& B10, int2& B11) {
        const int J = tc * 16;
        float4 uvA = *(const float4*)(uvp + J);
        float4 uvB = *(const float4*)(uvp + J + 8);
        float p00 = B00.x > 0 ? (uvA.x > th0 ? c10 * uvA.x : c20 * uvA.y) : 0.f;
        float p01 = B00.y > 0 ? (uvA.z > th0 ? c10 * uvA.z : c20 * uvA.w) : 0.f;
        float p08 = B01.x > 0 ? (uvB.x > th0 ? c10 * uvB.x : c20 * uvB.y) : 0.f;
        float p09 = B01.y > 0 ? (uvB.z > th0 ? c10 * uvB.z : c20 * uvB.w) : 0.f;
        float p10 = B10.x > 0 ? (uvA.x > th1 ? c11 * uvA.x : c21 * uvA.y) : 0.f;
        float p11 = B10.y > 0 ? (uvA.z > th1 ? c11 * uvA.z : c21 * uvA.w) : 0.f;
        float p18 = B11.x > 0 ? (uvB.x > th1 ? c11 * uvB.x : c21 * uvB.y) : 0.f;
        float p19 = B11.y > 0 ? (uvB.z > th1 ? c11 * uvB.z : c21 * uvB.w) : 0.f;

        // prefetch adj 2 tiles ahead into the same buffer set
        if (tc + 2 < NIT) {
            int o = (tc + 2) * 8;
            B00 = __ldcs(a00 + o); B01 = __ldcs(a00 + o + 4);
            B10 = __ldcs(a10 + o); B11 = __ldcs(a10 + o + 4);
        }

        // fp16 quantize A fragments; Z from the quantized values
        uint32_t ah0 = pkhf2(p00, p01), ah1 = pkhf2(p10, p11);
        uint32_t ah2 = pkhf2(p08, p09), ah3 = pkhf2(p18, p19);
        float2 q0 = uphf2(ah0), q1 = uphf2(ah1), q2 = uphf2(ah2), q3 = uphf2(ah3);
        z0 += (q0.x + q0.y) + (q2.x + q2.y);
        z1 += (q1.x + q1.y) + (q3.x + q3.y);

        const uint32_t base = lmBase + (uint32_t)((tc & 1) * 4096);
#pragma unroll
        for (int p = 0; p < 8; p++) {
            uint32_t b0, b1, b2, b3;
            ldsm_x4(base + p * 512, b0, b1, b2, b3);
            mma_fp16(acc[2 * p],     ah0, ah1, ah2, ah3, b0, b1);
            mma_fp16(acc[2 * p + 1], ah0, ah1, ah2, ah3, b2, b3);
        }
    };

#pragma unroll 1
    for (int t = 0; t < NIT; t += 2) {
        // even phase: stage t -> buf0, compute tile t-1 (buf1, adj Pb)
        __syncthreads();
        *(uint4*)(dst0) = cb;
        cb = src[2 * (t + 1) + hh];
        if (t > 0) compute(t - 1, Pb0, Pb1, Pb2, Pb3);

        // odd phase: stage t+1 -> buf1, compute tile t (buf0, adj Pa)
        __syncthreads();
        *(uint4*)(dst0 + 4096) = cb;
        if (t + 2 < NIT) cb = src[2 * (t + 2) + hh];
        compute(t, Pa0, Pa1, Pa2, Pa3);
    }
    __syncthreads();
    compute(NIT - 1, Pb0, Pb1, Pb2, Pb3);

    // Z reduction over the 4 lanes sharing a row
    z0 += __shfl_xor_sync(0xFFFFFFFFu, z0, 1);
    z0 += __shfl_xor_sync(0xFFFFFFFFu, z0, 2);
    z1 += __shfl_xor_sync(0xFFFFFFFFu, z1, 1);
    z1 += __shfl_xor_sync(0xFFFFFFFFu, z1, 2);
    const float iz0 = 1.0f / z0;
    const float iz1 = 1.0f / z1;

    float* o0 = out + ((size_t)(b * NN + r0)) * FF + 2 * c;
    float* o1 = out + ((size_t)(b * NN + r1)) * FF + 2 * c;
#pragma unroll
    for (int nt = 0; nt < 16; nt++) {
        float x0 = acc[nt][0] * iz0, x1 = acc[nt][1] * iz0;
        float y0 = acc[nt][2] * iz1, y1 = acc[nt][3] * iz1;
        x0 = x0 > 0.f ? x0 : (__expf(x0) - 1.0f);
        x1 = x1 > 0.f ? x1 : (__expf(x1) - 1.0f);
        y0 = y0 > 0.f ? y0 : (__expf(y0) - 1.0f);
        y1 = y1 > 0.f ? y1 : (__expf(y1) - 1.0f);
        *(float2*)(o0 + nt * 8) = make_float2(x0, x1);
        *(float2*)(o1 + nt * 8) = make_float2(y0, y1);
    }
}

// =====================================================================
extern "C" void kernel_launch(void* const* d_in, const int* in_sizes, int n_in,
                              void* d_out, int out_size) {
    const float* h   = (const float*)d_in[0];
    const int*   adj = (const int*)d_in[1];
    const float* W   = (const float*)d_in[2];
    const float* a   = (const float*)d_in[3];
    float* out = (float*)d_out;

    k_wh<<<dim3(NN / 32, BB), 256>>>(h, W, a);
    k_attn<<<dim3(NN / 128, BB), 256>>>(adj, out);
}

// round 11
// speedup vs baseline: 1.2530x; 1.0379x over previous
#include <cuda_runtime.h>
#include <cuda_fp16.h>
#include <cstdint>

#define BB 4
#define NN 4096
#define FF 128
#define NIT 256           // 4096 / 16 j-tiles

// ---------------- scratch (no allocations allowed) ----------------
__device__ uint4  g_Wh[(size_t)BB * FF * NN / 8];    // WhT fp16 [b][f][j], 4MB
__device__ float  g_si[BB * NN];
__device__ float2 g_uv[BB * NN];                     // {e^{sj}, e^{0.2 sj}}

// ---------------- helpers ----------------
__device__ __forceinline__ uint32_t smem_u32(const void* p) {
    uint32_t a;
    asm("{ .reg .u64 t; cvta.to.shared.u64 t, %1; cvt.u32.u64 %0, t; }" : "=r"(a) : "l"(p));
    return a;
}
__device__ __forceinline__ unsigned long long pack2(float lo, float hi) {
    unsigned long long r; asm("mov.b64 %0, {%1, %2};" : "=l"(r) : "f"(lo), "f"(hi)); return r;
}
__device__ __forceinline__ unsigned long long bcast2(float v) {
    unsigned long long r; asm("mov.b64 %0, {%1, %1};" : "=l"(r) : "f"(v)); return r;
}
__device__ __forceinline__ void fma2(unsigned long long& d, unsigned long long a, unsigned long long b) {
    asm("fma.rn.f32x2 %0, %1, %2, %0;" : "+l"(d) : "l"(a), "l"(b));
}
__device__ __forceinline__ float2 unpack2(unsigned long long v) {
    float2 f; asm("mov.b64 {%0, %1}, %2;" : "=f"(f.x), "=f"(f.y) : "l"(v)); return f;
}
// pack two floats -> fp16x2 (first arg low half), as uint32
__device__ __forceinline__ uint32_t pkhf2(float lo, float hi) {
    uint32_t r;
    asm("{ .reg .f16 l, h; cvt.rn.f16.f32 l, %1; cvt.rn.f16.f32 h, %2; mov.b32 %0, {l, h}; }"
        : "=r"(r) : "f"(lo), "f"(hi));
    return r;
}
// unpack fp16x2 -> two floats
__device__ __forceinline__ float2 uphf2(uint32_t v) {
    float2 f;
    asm("{ .reg .f16 l, h; mov.b32 {l, h}, %2; cvt.f32.f16 %0, l; cvt.f32.f16 %1, h; }"
        : "=f"(f.x), "=f"(f.y) : "r"(v));
    return f;
}
__device__ __forceinline__ void mma_fp16(float* c, uint32_t a0, uint32_t a1,
                                         uint32_t a2, uint32_t a3,
                                         uint32_t b0, uint32_t b1) {
    asm volatile(
        "mma.sync.aligned.m16n8k16.row.col.f32.f16.f16.f32 "
        "{%0,%1,%2,%3}, {%4,%5,%6,%7}, {%8,%9}, {%0,%1,%2,%3};"
        : "+f"(c[0]), "+f"(c[1]), "+f"(c[2]), "+f"(c[3])
        : "r"(a0), "r"(a1), "r"(a2), "r"(a3), "r"(b0), "r"(b1));
}
__device__ __forceinline__ void ldsm_x4(uint32_t addr, uint32_t& r0, uint32_t& r1,
                                        uint32_t& r2, uint32_t& r3) {
    asm volatile("ldmatrix.sync.aligned.m8n8.x4.shared.b16 {%0,%1,%2,%3}, [%4];"
                 : "=r"(r0), "=r"(r1), "=r"(r2), "=r"(r3) : "r"(addr));
}

// =====================================================================
// Kernel A: Wh = h @ W ; 32 rows x 128 f per CTA, 256 threads.
// Epilogue: fp16 store WhT[b][f][j] + si/sj/uv computed from fp32 acc.
// =====================================================================
__global__ void __launch_bounds__(256) k_wh(const float* __restrict__ h,
                                            const float* __restrict__ W,
                                            const float* __restrict__ a) {
    const int b = blockIdx.y;
    const int i0 = blockIdx.x * 32;

    __shared__ float hsT[32][40];    // [k][r], padded
    __shared__ float Ws[32][128];    // [k][f]
    __shared__ float aS[256];

    const int tid = threadIdx.x;
    aS[tid] = a[tid];
    const int fgrp = tid & 31, rgrp = tid >> 5;
    const int rbase = rgrp * 4, fbase = fgrp * 4;

    unsigned long long acc[4][2];
#pragma unroll
    for (int r = 0; r < 4; r++) { acc[r][0] = 0ULL; acc[r][1] = 0ULL; }

    for (int k0 = 0; k0 < FF; k0 += 32) {
        __syncthreads();
        {   // h tile: 32 rows x 32 k (one float4 per thread), transposed store
            int r = tid >> 3, kq = tid & 7;
            float4 v = *(const float4*)(h + ((size_t)(b * NN + i0 + r)) * FF + k0 + kq * 4);
            hsT[kq * 4 + 0][r] = v.x;
            hsT[kq * 4 + 1][r] = v.y;
            hsT[kq * 4 + 2][r] = v.z;
            hsT[kq * 4 + 3][r] = v.w;
        }
#pragma unroll
        for (int q = 0; q < 4; q++) {   // W chunk: 32 k x 128 f
            int idx = tid + 256 * q;
            int kk = idx >> 5, fq = idx & 31;
            *(float4*)&Ws[kk][fq * 4] = *(const float4*)(W + (size_t)(k0 + kk) * FF + fq * 4);
        }
        __syncthreads();

#pragma unroll 8
        for (int kk = 0; kk < 32; kk++) {
            float4 hr = *(float4*)&hsT[kk][rbase];
            float4 wf = *(float4*)&Ws[kk][fbase];
            unsigned long long w01 = pack2(wf.x, wf.y);
            unsigned long long w23 = pack2(wf.z, wf.w);
            float hv[4] = {hr.x, hr.y, hr.z, hr.w};
#pragma unroll
            for (int r = 0; r < 4; r++) {
                unsigned long long hb = bcast2(hv[r]);
                fma2(acc[r][0], hb, w01);
                fma2(acc[r][1], hb, w23);
            }
        }
    }

    float va[4][4];
#pragma unroll
    for (int r = 0; r < 4; r++) {
        float2 t0 = unpack2(acc[r][0]);
        float2 t1 = unpack2(acc[r][1]);
        va[r][0] = t0.x; va[r][1] = t0.y; va[r][2] = t1.x; va[r][3] = t1.y;
    }

    // fp16 store transposed: [b][f][j]
#pragma unroll
    for (int f = 0; f < 4; f++) {
        uint32_t h01 = pkhf2(va[0][f], va[1][f]);
        uint32_t h23 = pkhf2(va[2][f], va[3][f]);
        size_t idx = ((size_t)(b * FF) + fbase + f) * NN + i0 + rbase;  // fp16 elements
        *(uint2*)((__half*)g_Wh + idx) = make_uint2(h01, h23);
    }

    // si/sj from fp32 accumulators: warp reduce over fgrp (f dimension)
    float psi[4], psj[4];
#pragma unroll
    for (int r = 0; r < 4; r++) {
        float si = 0.f, sj = 0.f;
#pragma unroll
        for (int f = 0; f < 4; f++) {
            si += va[r][f] * aS[fbase + f];
            sj += va[r][f] * aS[FF + fbase + f];
        }
#pragma unroll
        for (int o = 16; o; o >>= 1) {
            si += __shfl_xor_sync(0xFFFFFFFFu, si, o);
            sj += __shfl_xor_sync(0xFFFFFFFFu, sj, o);
        }
        psi[r] = si; psj[r] = sj;
    }
    if (fgrp == 0) {
#pragma unroll
        for (int r = 0; r < 4; r++) {
            int row = b * NN + i0 + rbase + r;
            g_si[row] = psi[r];
            g_uv[row] = make_float2(__expf(psj[r]), __expf(0.2f * psj[r]));
        }
    }
}

// =====================================================================
// Kernel C: fused masked-softmax + P @ Wh via mma.sync fp16 (1-term) + ELU
// 128-thread CTA (4 warps, 64 i-rows) -> 2 CTAs resident per SM so
// independent CTAs hide each other's barrier/genP latency.
// B fragments via ldmatrix.x4; adj prefetched 2 tiles deep.
// =====================================================================
__global__ void __launch_bounds__(128, 2) k_attn(const int* __restrict__ adj,
                                                 float* __restrict__ out) {
    __shared__ float2 uvS[NN];          // 32 KB
    __shared__ uint4  stg4[512];        // 8 KB: 2 stages x 128 f x 32B
    char* stg = (char*)stg4;

    const int tid = threadIdx.x;
    const int lane = tid & 31, w = tid >> 5;     // w in 0..3
    const int c = lane & 3, fq = lane >> 2;
    const int b = blockIdx.y;
    const int i0 = blockIdx.x * 64;

#pragma unroll
    for (int k = 0; k < 32; k++) {
        int idx = tid + 128 * k;
        uvS[idx] = g_uv[b * NN + idx];
    }

    const int r0 = i0 + w * 16 + fq;
    const int r1 = r0 + 8;
    const float si0 = g_si[b * NN + r0];
    const float si1 = g_si[b * NN + r1];
    const float c10 = __expf(si0), c20 = __expf(0.2f * si0), th0 = __expf(-si0);
    const float c11 = __expf(si1), c21 = __expf(0.2f * si1), th1 = __expf(-si1);

    const int2* a00 = (const int2*)(adj + ((size_t)(b * NN + r0)) * NN + 2 * c);
    const int2* a10 = (const int2*)(adj + ((size_t)(b * NN + r1)) * NN + 2 * c);

    // staging role: thread -> full f row (two 16B chunks, chunk-swizzled)
    const int f = tid;
    const int sw = (f >> 2) & 1;
    const uint4* src = g_Wh + (size_t)(b * FF + f) * (NN / 8);   // 512 uint4 per row
    char* dstA = stg + f * 32 + 16 * sw;          // chunk 0
    char* dstB = stg + f * 32 + 16 * (sw ^ 1);    // chunk 1

    // ldmatrix per-lane base: lane&7 = matrix row (f offset), lane>>3 = matrix id
    // matrix id m: half = m&1 (j half), nto = m>>1 (nt offset within pair)
    const int l8 = lane & 7;
    const int mm = lane >> 3;
    const uint32_t stgU = smem_u32(stg);
    const uint32_t lmBase = stgU +
        (uint32_t)(l8 * 32 + 16 * ((mm & 1) ^ ((l8 >> 2) & 1)) + (mm >> 1) * 256);

    const float2* uvp = uvS + 2 * c;

    float acc[16][4];
#pragma unroll
    for (int nt = 0; nt < 16; nt++)
#pragma unroll
        for (int k = 0; k < 4; k++) acc[nt][k] = 0.f;
    float z0 = 0.f, z1 = 0.f;

    // prologue prefetch: adj for tiles 0 and 1, Wh chunks for tile 0
    int2 Pa0 = __ldcs(a00),     Pa1 = __ldcs(a00 + 4);
    int2 Pa2 = __ldcs(a10),     Pa3 = __ldcs(a10 + 4);
    int2 Pb0 = __ldcs(a00 + 8), Pb1 = __ldcs(a00 + 12);
    int2 Pb2 = __ldcs(a10 + 8), Pb3 = __ldcs(a10 + 12);
    uint4 cb0 = src[0], cb1 = src[1];

    auto compute = [&](int tc, int2& B00, int2& B01, int2& B10, int2& B11) {
        const int J = tc * 16;
        float4 uvA = *(const float4*)(uvp + J);
        float4 uvB = *(const float4*)(uvp + J + 8);
        float p00 = B00.x > 0 ? (uvA.x > th0 ? c10 * uvA.x : c20 * uvA.y) : 0.f;
        float p01 = B00.y > 0 ? (uvA.z > th0 ? c10 * uvA.z : c20 * uvA.w) : 0.f;
        float p08 = B01.x > 0 ? (uvB.x > th0 ? c10 * uvB.x : c20 * uvB.y) : 0.f;
        float p09 = B01.y > 0 ? (uvB.z > th0 ? c10 * uvB.z : c20 * uvB.w) : 0.f;
        float p10 = B10.x > 0 ? (uvA.x > th1 ? c11 * uvA.x : c21 * uvA.y) : 0.f;
        float p11 = B10.y > 0 ? (uvA.z > th1 ? c11 * uvA.z : c21 * uvA.w) : 0.f;
        float p18 = B11.x > 0 ? (uvB.x > th1 ? c11 * uvB.x : c21 * uvB.y) : 0.f;
        float p19 = B11.y > 0 ? (uvB.z > th1 ? c11 * uvB.z : c21 * uvB.w) : 0.f;

        // prefetch adj 2 tiles ahead into the same buffer set
        if (tc + 2 < NIT) {
            int o = (tc + 2) * 8;
            B00 = __ldcs(a00 + o); B01 = __ldcs(a00 + o + 4);
            B10 = __ldcs(a10 + o); B11 = __ldcs(a10 + o + 4);
        }

        // fp16 quantize A fragments; Z from the quantized values
        uint32_t ah0 = pkhf2(p00, p01), ah1 = pkhf2(p10, p11);
        uint32_t ah2 = pkhf2(p08, p09), ah3 = pkhf2(p18, p19);
        float2 q0 = uphf2(ah0), q1 = uphf2(ah1), q2 = uphf2(ah2), q3 = uphf2(ah3);
        z0 += (q0.x + q0.y) + (q2.x + q2.y);
        z1 += (q1.x + q1.y) + (q3.x + q3.y);

        const uint32_t base = lmBase + (uint32_t)((tc & 1) * 4096);
#pragma unroll
        for (int p = 0; p < 8; p++) {
            uint32_t b0, b1, b2, b3;
            ldsm_x4(base + p * 512, b0, b1, b2, b3);
            mma_fp16(acc[2 * p],     ah0, ah1, ah2, ah3, b0, b1);
            mma_fp16(acc[2 * p + 1], ah0, ah1, ah2, ah3, b2, b3);
        }
    };

#pragma unroll 1
    for (int t = 0; t < NIT; t += 2) {
        // even phase: stage t -> buf0, compute tile t-1 (buf1, adj Pb)
        __syncthreads();
        *(uint4*)(dstA) = cb0;
        *(uint4*)(dstB) = cb1;
        cb0 = src[2 * (t + 1)]; cb1 = src[2 * (t + 1) + 1];
        if (t > 0) compute(t - 1, Pb0, Pb1, Pb2, Pb3);

        // odd phase: stage t+1 -> buf1, compute tile t (buf0, adj Pa)
        __syncthreads();
        *(uint4*)(dstA + 4096) = cb0;
        *(uint4*)(dstB + 4096) = cb1;
        if (t + 2 < NIT) { cb0 = src[2 * (t + 2)]; cb1 = src[2 * (t + 2) + 1]; }
        compute(t, Pa0, Pa1, Pa2, Pa3);
    }
    __syncthreads();
    compute(NIT - 1, Pb0, Pb1, Pb2, Pb3);

    // Z reduction over the 4 lanes sharing a row
    z0 += __shfl_xor_sync(0xFFFFFFFFu, z0, 1);
    z0 += __shfl_xor_sync(0xFFFFFFFFu, z0, 2);
    z1 += __shfl_xor_sync(0xFFFFFFFFu, z1, 1);
    z1 += __shfl_xor_sync(0xFFFFFFFFu, z1, 2);
    const float iz0 = 1.0f / z0;
    const float iz1 = 1.0f / z1;

    float* o0 = out + ((size_t)(b * NN + r0)) * FF + 2 * c;
    float* o1 = out + ((size_t)(b * NN + r1)) * FF + 2 * c;
#pragma unroll
    for (int nt = 0; nt < 16; nt++) {
        float x0 = acc[nt][0] * iz0, x1 = acc[nt][1] * iz0;
        float y0 = acc[nt][2] * iz1, y1 = acc[nt][3] * iz1;
        x0 = x0 > 0.f ? x0 : (__expf(x0) - 1.0f);
        x1 = x1 > 0.f ? x1 : (__expf(x1) - 1.0f);
        y0 = y0 > 0.f ? y0 : (__expf(y0) - 1.0f);
        y1 = y1 > 0.f ? y1 : (__expf(y1) - 1.0f);
        *(float2*)(o0 + nt * 8) = make_float2(x0, x1);
        *(float2*)(o1 + nt * 8) = make_float2(y0, y1);
    }
}

// =====================================================================
extern "C" void kernel_launch(void* const* d_in, const int* in_sizes, int n_in,
                              void* d_out, int out_size) {
    const float* h   = (const float*)d_in[0];
    const int*   adj = (const int*)d_in[1];
    const float* W   = (const float*)d_in[2];
    const float* a   = (const float*)d_in[3];
    float* out = (float*)d_out;

    k_wh<<<dim3(NN / 32, BB), 256>>>(h, W, a);
    k_attn<<<dim3(NN / 64, BB), 128>>>(adj, out);
}